// round 11
// baseline (speedup 1.0000x reference)
#include <cuda_runtime.h>
#include <cuda_bf16.h>
#include <cstdint>

#define NN 200000
#define EE 3200000
#define BB 512
#define LL 1000

typedef unsigned long long ull;
typedef unsigned int uint;

// ------------------------ scratch (device globals, no allocs) ---------------
__device__ float g_dis[NN];
__device__ int   g_deg[NN];
__device__ float g_h[NN * 16];
__device__ float g_feat[NN * 16];
__device__ float g_agg[NN * 16];
__device__ float g_pool[BB * 16];
__device__ float g_t1[BB * 1024];
__device__ float g_xc[BB * 256];
__device__ float g_c1[BB * 32 * 331];
__device__ float g_c2[BB * 64 * 108];
__device__ float g_c3[BB * 128];
__device__ float g_f1[BB * 1024];
__device__ float g_f2[BB * 512];

// ------------------------ f32x2 helpers --------------------------------------
__device__ __forceinline__ ull pk2(float lo, float hi) {
    ull r; asm("mov.b64 %0, {%1, %2};" : "=l"(r) : "f"(lo), "f"(hi)); return r;
}
__device__ __forceinline__ float2 upk2(ull v) {
    float2 r; asm("mov.b64 {%0, %1}, %2;" : "=f"(r.x), "=f"(r.y) : "l"(v)); return r;
}
__device__ __forceinline__ void ffma2(ull& d, ull a, ull b) {
    asm("fma.rn.f32x2 %0, %1, %2, %0;" : "+l"(d) : "l"(a), "l"(b));
}

// ------------------------ tf32 helpers ---------------------------------------
__device__ __forceinline__ float tf32_hi(float v) {
    uint u; asm("cvt.rna.tf32.f32 %0, %1;" : "=r"(u) : "f"(v));
    return __uint_as_float(u);
}
__device__ __forceinline__ void mma_tf32(float d[4], uint a0, uint a1, uint a2, uint a3,
                                         uint b0, uint b1) {
    asm volatile("mma.sync.aligned.m16n8k8.row.col.f32.tf32.tf32.f32 "
                 "{%0,%1,%2,%3}, {%4,%5,%6,%7}, {%8,%9}, {%0,%1,%2,%3};"
                 : "+f"(d[0]), "+f"(d[1]), "+f"(d[2]), "+f"(d[3])
                 : "r"(a0), "r"(a1), "r"(a2), "r"(a3), "r"(b0), "r"(b1));
}

// ------------------------ graph branch --------------------------------------
__global__ void deg_kernel(const int* __restrict__ ei, int* __restrict__ deg) {
    int e = blockIdx.x * blockDim.x + threadIdx.x;
    if (e >= EE) return;
    atomicAdd(&deg[ei[EE + e]], 1);
}

__global__ void dis_kernel(const int* __restrict__ deg, float* __restrict__ dis) {
    int i = blockIdx.x * blockDim.x + threadIdx.x;
    if (i >= NN) return;
    dis[i] = rsqrtf((float)deg[i] + 1.0f);
}

__global__ void transform1(const float* __restrict__ x, const float* __restrict__ W,
                           const float* __restrict__ dis, float* __restrict__ hs) {
    __shared__ float Ws[16];
    int tid = threadIdx.x;
    if (tid < 16) Ws[tid] = W[tid];
    __syncthreads();
    int i = blockIdx.x * blockDim.x + tid;
    if (i >= NN) return;
    float xi[4];
#pragma unroll
    for (int f = 0; f < 4; f++) xi[f] = x[(size_t)i * 4 + f];
    float dd = dis[i];
#pragma unroll
    for (int fo = 0; fo < 4; fo++) {
        float s = 0.f;
#pragma unroll
        for (int fi = 0; fi < 4; fi++) s = fmaf(xi[fi], Ws[fi * 4 + fo], s);
        hs[(size_t)i * 4 + fo] = dd * s;
    }
}

template <int F>
__global__ void scatter_kernel(const int* __restrict__ ei, const float* __restrict__ hs,
                               float* __restrict__ agg) {
    int e = blockIdx.x * blockDim.x + threadIdx.x;
    if (e >= EE) return;
    int s = __ldg(&ei[e]);
    int d = __ldg(&ei[EE + e]);
    const float4* p = reinterpret_cast<const float4*>(hs + (size_t)s * F);
    float* ad = agg + (size_t)d * F;
#pragma unroll
    for (int q = 0; q < F / 4; q++) {
        float4 m = p[q];
        asm volatile("red.global.add.v4.f32 [%0], {%1,%2,%3,%4};"
                     :: "l"(ad + q * 4), "f"(m.x), "f"(m.y), "f"(m.z), "f"(m.w)
                     : "memory");
    }
}

template <int F, int FO>
__global__ void combine_transform(const float* __restrict__ agg, const float* __restrict__ hs,
                                  const float* __restrict__ dis, const float* __restrict__ bias,
                                  const float* __restrict__ W, float* __restrict__ out) {
    __shared__ float Ws[F * FO];
    __shared__ float bs[F];
    int tid = threadIdx.x;
    if (tid < F * FO) Ws[tid] = W[tid];
    if (tid < F) bs[tid] = bias[tid];
    __syncthreads();
    int i = blockIdx.x * blockDim.x + tid;
    if (i >= NN) return;
    float dd = dis[i];
    float v[F];
#pragma unroll
    for (int f = 0; f < F; f++)
        v[f] = fmaxf(dd * (agg[(size_t)i * F + f] + hs[(size_t)i * F + f]) + bs[f], 0.f);
#pragma unroll
    for (int fo = 0; fo < FO; fo++) {
        float s = 0.f;
#pragma unroll
        for (int f = 0; f < F; f++) s = fmaf(v[f], Ws[f * FO + fo], s);
        out[(size_t)i * FO + fo] = dd * s;
    }
}

__global__ void combine_pool(const float* __restrict__ agg, const float* __restrict__ hs,
                             const float* __restrict__ dis, const float* __restrict__ bias,
                             const int* __restrict__ batch, float* __restrict__ pool) {
    __shared__ float bs[16];
    int tid = threadIdx.x;
    if (tid < 16) bs[tid] = bias[tid];
    __syncthreads();
    int i = blockIdx.x * blockDim.x + tid;
    if (i >= NN) return;
    float dd = dis[i];
    float v[16];
#pragma unroll
    for (int f = 0; f < 16; f++)
        v[f] = fmaxf(dd * (agg[(size_t)i * 16 + f] + hs[(size_t)i * 16 + f]) + bs[f], 0.f);
    int bb = batch[i];
    unsigned m = __activemask();
    bool uni = false;
    if (m == 0xffffffffu) {
        int bb0 = __shfl_sync(0xffffffffu, bb, 0);
        uni = __all_sync(0xffffffffu, bb == bb0);
    }
    int* p = reinterpret_cast<int*>(pool + (size_t)bb * 16);
    if (uni) {
#pragma unroll
        for (int f = 0; f < 16; f++) {
            float t = v[f];
#pragma unroll
            for (int o = 16; o; o >>= 1) t = fmaxf(t, __shfl_xor_sync(0xffffffffu, t, o));
            v[f] = t;
        }
        if ((tid & 31) == 0)
#pragma unroll
            for (int f = 0; f < 16; f++) atomicMax(&p[f], __float_as_int(v[f]));
    } else {
#pragma unroll
        for (int f = 0; f < 16; f++) atomicMax(&p[f], __float_as_int(v[f]));
    }
}

// ------------------------ generic GEMM (f32x2) -------------------------------
__global__ void gemm_kernel(const float* __restrict__ A, const float* __restrict__ W,
                            const float* __restrict__ bias, float* __restrict__ C,
                            int M, int K, int Nc, int ldc, int coloff, int relu) {
    const int BM = 64, BN = 64, BK = 8;
    __shared__ __align__(16) float As[BK][BM];
    __shared__ __align__(16) float Bs[BK][BN];
    int tid = threadIdx.x;
    int tc = tid & 15, tr = tid >> 4;
    int brow = blockIdx.y * BM, bcol = blockIdx.x * BN;
    ull acc[4][2] = {};
    for (int k0 = 0; k0 < K; k0 += BK) {
        for (int i = tid; i < BM * BK; i += 256) {
            int kk = i & 7, m = i >> 3;
            int gr = brow + m, gc = k0 + kk;
            As[kk][m] = (gr < M && gc < K) ? A[(size_t)gr * K + gc] : 0.f;
        }
        for (int i = tid; i < BN * BK; i += 256) {
            int n = i & 63, kk = i >> 6;
            int gc = bcol + n, gr = k0 + kk;
            Bs[kk][n] = (gr < K && gc < Nc) ? W[(size_t)gr * Nc + gc] : 0.f;
        }
        __syncthreads();
#pragma unroll
        for (int kk = 0; kk < BK; kk++) {
            ull b0 = *reinterpret_cast<const ull*>(&Bs[kk][tc * 4]);
            ull b1 = *reinterpret_cast<const ull*>(&Bs[kk][tc * 4 + 2]);
            float4 av = *reinterpret_cast<const float4*>(&As[kk][tr * 4]);
            float aa[4] = {av.x, av.y, av.z, av.w};
#pragma unroll
            for (int u = 0; u < 4; u++) {
                ull a2 = pk2(aa[u], aa[u]);
                ffma2(acc[u][0], b0, a2);
                ffma2(acc[u][1], b1, a2);
            }
        }
        __syncthreads();
    }
#pragma unroll
    for (int u = 0; u < 4; u++) {
        int r = brow + tr * 4 + u;
        if (r >= M) continue;
#pragma unroll
        for (int v2 = 0; v2 < 2; v2++) {
            float2 pv = upk2(acc[u][v2]);
            float vals[2] = {pv.x, pv.y};
#pragma unroll
            for (int w = 0; w < 2; w++) {
                int c = bcol + tc * 4 + v2 * 2 + w;
                if (c >= Nc) continue;
                float val = vals[w] + bias[c];
                if (relu) val = fmaxf(val, 0.f);
                C[(size_t)r * ldc + coloff + c] = val;
            }
        }
    }
}

// ------------------------ conv1 (scalar f32x2) -------------------------------
__device__ __forceinline__ void load_e10(const float* __restrict__ xA, ull e[10]) {
    const ulonglong2* pA = reinterpret_cast<const ulonglong2*>(xA);
#pragma unroll
    for (int i = 0; i < 5; i++) {
        ulonglong2 va = pA[i]; e[2 * i] = va.x; e[2 * i + 1] = va.y;
    }
}
__device__ __forceinline__ void make_o8(const ull e[10], ull o[8]) {
#pragma unroll
    for (int j = 0; j < 8; j++)
        o[j] = (e[j] >> 32) | (e[j + 1] << 32);
}

__device__ __forceinline__ void ic_upd_1oc(const float* __restrict__ xA,
                                           const float* __restrict__ w, ull a0[5]) {
    ull e[10], o[8];
    load_e10(xA, e); make_o8(e, o);
#pragma unroll
    for (int k = 0; k < 8; k++) {
        float wv = w[k * 33];
        ull w2 = pk2(wv, wv);
        const ull* xpp = (k & 1) ? &o[k >> 1] : &e[k >> 1];
#pragma unroll
        for (int j = 0; j < 5; j++) ffma2(a0[j], xpp[j], w2);
    }
}

__device__ __forceinline__ void unpack9(const ull acc[5], float a[9]) {
#pragma unroll
    for (int j = 0; j < 4; j++) {
        float2 t = upk2(acc[j]);
        a[2 * j] = t.x; a[2 * j + 1] = t.y;
    }
    a[8] = upk2(acc[4]).x;
}

__global__ void conv1_kernel(const float* __restrict__ tgt, const float* __restrict__ K1,
                             const float* __restrict__ cb1, float* __restrict__ out) {
    __shared__ __align__(16) float inA[5 * 8 * 20];
    __shared__ float w_s[40 * 33];
    __shared__ float b_s[32];
    int b = blockIdx.x;
    int g0 = blockIdx.y * 8;
    int tx = threadIdx.x, ty = threadIdx.y;
    int tid = ty * 32 + tx;
    int L0 = g0 * 9;
    for (int i = tid; i < 800; i += 256) {
        int c = i / 160, r = i % 160, t = r / 20, j = r % 20;
        int l = L0 + t * 9 + j;
        inA[i] = (l < LL) ? tgt[(size_t)b * (LL * 5) + l * 5 + c] : 0.f;
    }
    for (int i = tid; i < 2048; i += 256) {
        int oc = i >> 6, r = i & 63;
        if (r < 40) w_s[r * 33 + oc] = K1[oc * 40 + r];
    }
    if (tid < 32) b_s[tid] = cb1[tid];
    __syncthreads();

    ull acc[5] = {};
#pragma unroll
    for (int ic = 0; ic < 5; ic++)
        ic_upd_1oc(&inA[(ic * 8 + ty) * 20], &w_s[ic * 8 * 33 + tx], acc);
    float a[9]; unpack9(acc, a);
    float bb = b_s[tx];
    int grp = g0 + ty;
#pragma unroll
    for (int p = 0; p < 3; p++) {
        int po = grp * 3 + p;
        if (po < 331) {
            float v = fmaxf(fmaxf(a[3 * p], a[3 * p + 1]), a[3 * p + 2]) + bb;
            out[((size_t)b * 32 + tx) * 331 + po] = fmaxf(v, 0.f);
        }
    }
}

// ------------------------ conv2: 3xTF32 implicit GEMM ------------------------
// Block (b, z): D[64 oc][168 pos], pos base = z*168. 324 = 108*3 exactly.
// smem: xh[32*200] | xl[32*200] | wh[64*33] | wl[64*33]
#define C2M_XL  6400
#define C2M_WH  12800
#define C2M_WL  (12800 + 2112)
#define CONV2M_SMEM ((12800 + 2 * 2112) * 4)
__global__ void __launch_bounds__(256, 2) conv2_mma(
        const float* __restrict__ c1, const float* __restrict__ K2,
        const float* __restrict__ cb2, float* __restrict__ out) {
    extern __shared__ __align__(16) float sm[];
    float* xh = sm;
    float* xl = sm + C2M_XL;
    float* wh = sm + C2M_WH;
    float* wl = sm + C2M_WL;
    int b = blockIdx.x, z = blockIdx.y;
    int tid = threadIdx.x;
    int lane = tid & 31, w = tid >> 5;
    int wm = w >> 2, wn = w & 3;            // 2 m-groups x 4 n-quarters
    int g = lane >> 2, tg = lane & 3;
    int base = z * 168;

    // stage x (hi/lo tf32 split), rows padded to 200 with zeros
    for (int i = tid; i < 6400; i += 256) {
        int ic = i / 200, j = i % 200;
        int l = base + j;
        float v = (l < 331) ? c1[((size_t)b * 32 + ic) * 331 + l] : 0.f;
        float h = tf32_hi(v);
        xh[i] = h;
        xl[i] = tf32_hi(v - h);
    }

    float acc[2][6][4] = {};
    for (int s = 0; s < 8; s++) {
        __syncthreads();
        // weight chunk [64 oc][32 r], r = s*32 .. s*32+31, hi/lo split
        for (int i = tid; i < 2048; i += 256) {
            int oc = i >> 5, rr = i & 31;
            float v = K2[(size_t)oc * 256 + s * 32 + rr];
            float h = tf32_hi(v);
            wh[oc * 33 + rr] = h;
            wl[oc * 33 + rr] = tf32_hi(v - h);
        }
        __syncthreads();
#pragma unroll
        for (int ks = 0; ks < 4; ks++) {
            int ic = s * 4 + ks;
            const float* xrh = xh + ic * 200;
            const float* xrl = xl + ic * 200;
            uint bh0[6], bh1[6], bl0[6], bl1[6];
#pragma unroll
            for (int nt = 0; nt < 6; nt++) {
                int ai = (wn * 6 + nt) * 8 + g + tg;
                bh0[nt] = __float_as_uint(xrh[ai]);
                bh1[nt] = __float_as_uint(xrh[ai + 4]);
                bl0[nt] = __float_as_uint(xrl[ai]);
                bl1[nt] = __float_as_uint(xrl[ai + 4]);
            }
#pragma unroll
            for (int mt = 0; mt < 2; mt++) {
                int ocr = wm * 32 + mt * 16 + g;
                int col = ks * 8 + tg;
                uint ah0 = __float_as_uint(wh[ocr * 33 + col]);
                uint ah1 = __float_as_uint(wh[(ocr + 8) * 33 + col]);
                uint ah2 = __float_as_uint(wh[ocr * 33 + col + 4]);
                uint ah3 = __float_as_uint(wh[(ocr + 8) * 33 + col + 4]);
                uint al0 = __float_as_uint(wl[ocr * 33 + col]);
                uint al1 = __float_as_uint(wl[(ocr + 8) * 33 + col]);
                uint al2 = __float_as_uint(wl[ocr * 33 + col + 4]);
                uint al3 = __float_as_uint(wl[(ocr + 8) * 33 + col + 4]);
#pragma unroll
                for (int nt = 0; nt < 6; nt++) {
                    mma_tf32(acc[mt][nt], al0, al1, al2, al3, bh0[nt], bh1[nt]);
                    mma_tf32(acc[mt][nt], ah0, ah1, ah2, ah3, bl0[nt], bl1[nt]);
                    mma_tf32(acc[mt][nt], ah0, ah1, ah2, ah3, bh0[nt], bh1[nt]);
                }
            }
        }
    }
    __syncthreads();
    // dump D[64][200] into the x region (64*200 = 12800 floats exactly)
    float* dump = sm;
#pragma unroll
    for (int mt = 0; mt < 2; mt++) {
        int ocr = wm * 32 + mt * 16 + g;
#pragma unroll
        for (int nt = 0; nt < 6; nt++) {
            int n0 = (wn * 6 + nt) * 8 + 2 * tg;
            dump[ocr * 200 + n0]           = acc[mt][nt][0];
            dump[ocr * 200 + n0 + 1]       = acc[mt][nt][1];
            dump[(ocr + 8) * 200 + n0]     = acc[mt][nt][2];
            dump[(ocr + 8) * 200 + n0 + 1] = acc[mt][nt][3];
        }
    }
    __syncthreads();
    if (tid < 64) {
        float bb = cb2[tid];
        const float* row = dump + tid * 200;
        float* orow = out + ((size_t)b * 64 + tid) * 108 + z * 56;
#pragma unroll
        for (int g2 = 0; g2 < 56; g2++) {
            int po = z * 56 + g2;
            if (po < 108) {
                float v = fmaxf(fmaxf(row[3 * g2], row[3 * g2 + 1]), row[3 * g2 + 2]) + bb;
                orow[g2] = fmaxf(v, 0.f);
            }
        }
    }
}

// ------------------------ conv3: 3xTF32 implicit GEMM ------------------------
#define C3M_XL  7168
#define C3M_WH  14336
#define C3M_WL  (14336 + 4224)
#define CONV3M_SMEM ((14336 + 2 * 4224) * 4)
__global__ void __launch_bounds__(256, 2) conv3_mma(
        const float* __restrict__ c2, const float* __restrict__ K3,
        const float* __restrict__ cb3, float* __restrict__ c3) {
    extern __shared__ __align__(16) float sm[];
    float* xh = sm;
    float* xl = sm + C3M_XL;
    float* wh = sm + C3M_WH;
    float* wl = sm + C3M_WL;
    int b = blockIdx.x;
    int tid = threadIdx.x;
    int lane = tid & 31, w = tid >> 5;
    int wm = w >> 1, wn = w & 1;           // 4 m-groups x 2 n-halves
    int g = lane >> 2, tg = lane & 3;

    for (int i = tid; i < 7168; i += 256) {
        int ic = i / 112, l = i % 112;
        float v = (l < 108) ? c2[(size_t)b * 6912 + ic * 108 + l] : 0.f;
        float h = tf32_hi(v);
        xh[i] = h;
        xl[i] = tf32_hi(v - h);
    }

    float acc[2][7][4] = {};
    for (int s = 0; s < 16; s++) {
        __syncthreads();
        for (int i = tid; i < 4096; i += 256) {
            int oc = i >> 5, rr = i & 31;
            float v = K3[(size_t)oc * 512 + s * 32 + rr];
            float h = tf32_hi(v);
            wh[oc * 33 + rr] = h;
            wl[oc * 33 + rr] = tf32_hi(v - h);
        }
        __syncthreads();
#pragma unroll
        for (int ks = 0; ks < 4; ks++) {
            int ic = s * 4 + ks;
            const float* xrh = xh + ic * 112;
            const float* xrl = xl + ic * 112;
            uint bh0[7], bh1[7], bl0[7], bl1[7];
#pragma unroll
            for (int nt = 0; nt < 7; nt++) {
                int ai = (wn * 7 + nt) * 8 + g + tg;
                bh0[nt] = __float_as_uint(xrh[ai]);
                bh1[nt] = __float_as_uint(xrh[ai + 4]);
                bl0[nt] = __float_as_uint(xrl[ai]);
                bl1[nt] = __float_as_uint(xrl[ai + 4]);
            }
#pragma unroll
            for (int mt = 0; mt < 2; mt++) {
                int ocr = wm * 32 + mt * 16 + g;
                int col = ks * 8 + tg;
                uint ah0 = __float_as_uint(wh[ocr * 33 + col]);
                uint ah1 = __float_as_uint(wh[(ocr + 8) * 33 + col]);
                uint ah2 = __float_as_uint(wh[ocr * 33 + col + 4]);
                uint ah3 = __float_as_uint(wh[(ocr + 8) * 33 + col + 4]);
                uint al0 = __float_as_uint(wl[ocr * 33 + col]);
                uint al1 = __float_as_uint(wl[(ocr + 8) * 33 + col]);
                uint al2 = __float_as_uint(wl[ocr * 33 + col + 4]);
                uint al3 = __float_as_uint(wl[(ocr + 8) * 33 + col + 4]);
#pragma unroll
                for (int nt = 0; nt < 7; nt++) {
                    mma_tf32(acc[mt][nt], al0, al1, al2, al3, bh0[nt], bh1[nt]);
                    mma_tf32(acc[mt][nt], ah0, ah1, ah2, ah3, bl0[nt], bl1[nt]);
                    mma_tf32(acc[mt][nt], ah0, ah1, ah2, ah3, bh0[nt], bh1[nt]);
                }
            }
        }
    }
    __syncthreads();
    float* dump = sm;
#pragma unroll
    for (int mt = 0; mt < 2; mt++) {
        int ocr = wm * 32 + mt * 16 + g;
#pragma unroll
        for (int nt = 0; nt < 7; nt++) {
            int n0 = (wn * 7 + nt) * 8 + 2 * tg;
            dump[ocr * 112 + n0]           = acc[mt][nt][0];
            dump[ocr * 112 + n0 + 1]       = acc[mt][nt][1];
            dump[(ocr + 8) * 112 + n0]     = acc[mt][nt][2];
            dump[(ocr + 8) * 112 + n0 + 1] = acc[mt][nt][3];
        }
    }
    __syncthreads();
    if (tid < 128) {
        float bb = cb3[tid];
        const float* row = dump + tid * 112;
        float ssum = 0.f;
#pragma unroll
        for (int gp = 0; gp < 33; gp++) {
            float v = fmaxf(fmaxf(row[3 * gp], row[3 * gp + 1]), row[3 * gp + 2]) + bb;
            ssum += fmaxf(v, 0.f);
        }
        c3[(size_t)b * 128 + tid] = ssum * (1.0f / 33.0f);
    }
}

// ------------------------ stream fork/join context --------------------------
struct Ctx {
    cudaStream_t s2 = nullptr;
    cudaEvent_t eF = nullptr, eJ = nullptr;
    bool ok = false;
    Ctx() {
        ok = (cudaStreamCreateWithFlags(&s2, cudaStreamNonBlocking) == cudaSuccess) &&
             (cudaEventCreateWithFlags(&eF, cudaEventDisableTiming) == cudaSuccess) &&
             (cudaEventCreateWithFlags(&eJ, cudaEventDisableTiming) == cudaSuccess);
    }
};
static Ctx g_ctx;

// ------------------------ host orchestration --------------------------------
extern "C" void kernel_launch(void* const* d_in, const int* in_sizes, int n_in,
                              void* d_out, int out_size) {
    const float* x    = (const float*)d_in[0];
    const int*   ei   = (const int*)d_in[1];
    const int*   batch= (const int*)d_in[2];
    const float* tgt  = (const float*)d_in[3];
    const float* W1 = (const float*)d_in[4];   const float* b1 = (const float*)d_in[5];
    const float* W2 = (const float*)d_in[6];   const float* b2 = (const float*)d_in[7];
    const float* W3 = (const float*)d_in[8];   const float* b3 = (const float*)d_in[9];
    const float* Wg1= (const float*)d_in[10];  const float* bg1= (const float*)d_in[11];
    const float* Wg2= (const float*)d_in[12];  const float* bg2= (const float*)d_in[13];
    const float* K1 = (const float*)d_in[14];  const float* cb1= (const float*)d_in[15];
    const float* K2 = (const float*)d_in[16];  const float* cb2= (const float*)d_in[17];
    const float* K3 = (const float*)d_in[18];  const float* cb3= (const float*)d_in[19];
    const float* Wxt= (const float*)d_in[20];  const float* bxt= (const float*)d_in[21];
    const float* Wf1= (const float*)d_in[22];  const float* bf1= (const float*)d_in[23];
    const float* Wf2= (const float*)d_in[24];  const float* bf2= (const float*)d_in[25];
    const float* Wo = (const float*)d_in[26];  const float* bo = (const float*)d_in[27];
    float* out = (float*)d_out;

    float *p_dis, *p_h, *p_feat, *p_agg, *p_pool, *p_t1, *p_xc, *p_c1, *p_c2, *p_c3, *p_f1, *p_f2;
    int* p_deg;
    cudaGetSymbolAddress((void**)&p_dis, g_dis);
    cudaGetSymbolAddress((void**)&p_deg, g_deg);
    cudaGetSymbolAddress((void**)&p_h, g_h);
    cudaGetSymbolAddress((void**)&p_feat, g_feat);
    cudaGetSymbolAddress((void**)&p_agg, g_agg);
    cudaGetSymbolAddress((void**)&p_pool, g_pool);
    cudaGetSymbolAddress((void**)&p_t1, g_t1);
    cudaGetSymbolAddress((void**)&p_xc, g_xc);
    cudaGetSymbolAddress((void**)&p_c1, g_c1);
    cudaGetSymbolAddress((void**)&p_c2, g_c2);
    cudaGetSymbolAddress((void**)&p_c3, g_c3);
    cudaGetSymbolAddress((void**)&p_f1, g_f1);
    cudaGetSymbolAddress((void**)&p_f2, g_f2);

    const int TPB = 256;
    const int gE = (EE + TPB - 1) / TPB;
    const int gN = (NN + TPB - 1) / TPB;

    bool fork = g_ctx.ok;
    cudaStream_t sg = fork ? g_ctx.s2 : (cudaStream_t)0;

    if (fork) {
        cudaEventRecord(g_ctx.eF, 0);
        cudaStreamWaitEvent(sg, g_ctx.eF, 0);
    }

    cudaFuncSetAttribute(conv2_mma, cudaFuncAttributeMaxDynamicSharedMemorySize, CONV2M_SMEM);
    cudaFuncSetAttribute(conv3_mma, cudaFuncAttributeMaxDynamicSharedMemorySize, CONV3M_SMEM);

    // Submission order: conv2_mma is the 6th launch (ncu -s 5 -c 1 window).
    cudaMemsetAsync(p_deg, 0, NN * sizeof(int), sg);                                 // 1
    deg_kernel<<<gE, TPB, 0, sg>>>(ei, p_deg);                                       // 2
    conv1_kernel<<<dim3(BB, 14), dim3(32, 8)>>>(tgt, K1, cb1, p_c1);                 // 3
    cudaMemsetAsync(p_c3, 0, BB * 128 * sizeof(float));                              // 4
    dis_kernel<<<gN, TPB, 0, sg>>>(p_deg, p_dis);                                    // 5
    conv2_mma<<<dim3(BB, 2), 256, CONV2M_SMEM>>>(p_c1, K2, cb2, p_c2);               // 6 <- profiled
    conv3_mma<<<BB, 256, CONV3M_SMEM>>>(p_c2, K3, cb3, p_c3);
    gemm_kernel<<<dim3(2, 8), 256>>>(p_c3, Wxt, bxt, p_xc, BB, 128, 128, 256, 128, 1);

    // ---- graph branch (stream sg) ----
    transform1<<<gN, TPB, 0, sg>>>(x, W1, p_dis, p_h);
    cudaMemsetAsync(p_agg, 0, (size_t)NN * 4 * sizeof(float), sg);
    scatter_kernel<4><<<gE, TPB, 0, sg>>>(ei, p_h, p_agg);
    combine_transform<4, 8><<<gN, TPB, 0, sg>>>(p_agg, p_h, p_dis, b1, W2, p_feat);

    cudaMemsetAsync(p_agg, 0, (size_t)NN * 8 * sizeof(float), sg);
    scatter_kernel<8><<<gE, TPB, 0, sg>>>(ei, p_feat, p_agg);
    combine_transform<8, 16><<<gN, TPB, 0, sg>>>(p_agg, p_feat, p_dis, b2, W3, p_h);

    cudaMemsetAsync(p_agg, 0, (size_t)NN * 16 * sizeof(float), sg);
    scatter_kernel<16><<<gE, TPB, 0, sg>>>(ei, p_h, p_agg);
    cudaMemsetAsync(p_pool, 0, BB * 16 * sizeof(float), sg);
    combine_pool<<<gN, TPB, 0, sg>>>(p_agg, p_h, p_dis, b3, batch, p_pool);

    gemm_kernel<<<dim3(16, 8), 256, 0, sg>>>(p_pool, Wg1, bg1, p_t1, BB, 16, 1024, 1024, 0, 1);
    gemm_kernel<<<dim3(2, 8), 256, 0, sg>>>(p_t1, Wg2, bg2, p_xc, BB, 1024, 128, 256, 0, 0);
    if (fork) cudaEventRecord(g_ctx.eJ, sg);

    // ---- join + fusion head (stream 0) ----
    if (fork) cudaStreamWaitEvent(0, g_ctx.eJ, 0);
    gemm_kernel<<<dim3(16, 8), 256>>>(p_xc, Wf1, bf1, p_f1, BB, 256, 1024, 1024, 0, 1);
    gemm_kernel<<<dim3(8, 8), 256>>>(p_f1, Wf2, bf2, p_f2, BB, 1024, 512, 512, 0, 1);
    gemm_kernel<<<dim3(1, 8), 256>>>(p_f2, Wo, bo, out, BB, 512, 2, 2, 0, 0);
}

// round 12
// speedup vs baseline: 1.0339x; 1.0339x over previous
#include <cuda_runtime.h>
#include <cuda_bf16.h>
#include <cstdint>

#define NN 200000
#define EE 3200000
#define BB 512
#define LL 1000

typedef unsigned long long ull;
typedef unsigned int uint;

// ------------------------ scratch (device globals, no allocs) ---------------
__device__ float g_dis[NN];
__device__ int   g_deg[NN];
__device__ float g_h[NN * 16];
__device__ float g_feat[NN * 16];
__device__ float g_agg[NN * 16];
__device__ float g_pool[BB * 16];
__device__ float g_t1[BB * 1024];
__device__ float g_xc[BB * 256];
__device__ float g_c1[BB * 32 * 331];
__device__ float g_c2[BB * 64 * 108];
__device__ float g_c3[BB * 128];
__device__ float g_f1[BB * 1024];
__device__ float g_f2[BB * 512];

// ------------------------ f32x2 helpers --------------------------------------
__device__ __forceinline__ ull pk2(float lo, float hi) {
    ull r; asm("mov.b64 %0, {%1, %2};" : "=l"(r) : "f"(lo), "f"(hi)); return r;
}
__device__ __forceinline__ float2 upk2(ull v) {
    float2 r; asm("mov.b64 {%0, %1}, %2;" : "=f"(r.x), "=f"(r.y) : "l"(v)); return r;
}
__device__ __forceinline__ void ffma2(ull& d, ull a, ull b) {
    asm("fma.rn.f32x2 %0, %1, %2, %0;" : "+l"(d) : "l"(a), "l"(b));
}

// ------------------------ tf32 helpers ---------------------------------------
__device__ __forceinline__ float tf32_hi(float v) {
    uint u; asm("cvt.rna.tf32.f32 %0, %1;" : "=r"(u) : "f"(v));
    return __uint_as_float(u);
}
__device__ __forceinline__ void mma_tf32(float d[4], uint a0, uint a1, uint a2, uint a3,
                                         uint b0, uint b1) {
    asm volatile("mma.sync.aligned.m16n8k8.row.col.f32.tf32.tf32.f32 "
                 "{%0,%1,%2,%3}, {%4,%5,%6,%7}, {%8,%9}, {%0,%1,%2,%3};"
                 : "+f"(d[0]), "+f"(d[1]), "+f"(d[2]), "+f"(d[3])
                 : "r"(a0), "r"(a1), "r"(a2), "r"(a3), "r"(b0), "r"(b1));
}

// ------------------------ graph branch --------------------------------------
__global__ void deg_kernel(const int* __restrict__ ei, int* __restrict__ deg) {
    int e = blockIdx.x * blockDim.x + threadIdx.x;
    if (e >= EE) return;
    atomicAdd(&deg[ei[EE + e]], 1);
}

__global__ void dis_kernel(const int* __restrict__ deg, float* __restrict__ dis) {
    int i = blockIdx.x * blockDim.x + threadIdx.x;
    if (i >= NN) return;
    dis[i] = rsqrtf((float)deg[i] + 1.0f);
}

__global__ void transform1(const float* __restrict__ x, const float* __restrict__ W,
                           const float* __restrict__ dis, float* __restrict__ hs) {
    __shared__ float Ws[16];
    int tid = threadIdx.x;
    if (tid < 16) Ws[tid] = W[tid];
    __syncthreads();
    int i = blockIdx.x * blockDim.x + tid;
    if (i >= NN) return;
    float xi[4];
#pragma unroll
    for (int f = 0; f < 4; f++) xi[f] = x[(size_t)i * 4 + f];
    float dd = dis[i];
#pragma unroll
    for (int fo = 0; fo < 4; fo++) {
        float s = 0.f;
#pragma unroll
        for (int fi = 0; fi < 4; fi++) s = fmaf(xi[fi], Ws[fi * 4 + fo], s);
        hs[(size_t)i * 4 + fo] = dd * s;
    }
}

template <int F>
__global__ void scatter_kernel(const int* __restrict__ ei, const float* __restrict__ hs,
                               float* __restrict__ agg) {
    int e = blockIdx.x * blockDim.x + threadIdx.x;
    if (e >= EE) return;
    int s = __ldg(&ei[e]);
    int d = __ldg(&ei[EE + e]);
    const float4* p = reinterpret_cast<const float4*>(hs + (size_t)s * F);
    float* ad = agg + (size_t)d * F;
#pragma unroll
    for (int q = 0; q < F / 4; q++) {
        float4 m = p[q];
        asm volatile("red.global.add.v4.f32 [%0], {%1,%2,%3,%4};"
                     :: "l"(ad + q * 4), "f"(m.x), "f"(m.y), "f"(m.z), "f"(m.w)
                     : "memory");
    }
}

template <int F, int FO>
__global__ void combine_transform(const float* __restrict__ agg, const float* __restrict__ hs,
                                  const float* __restrict__ dis, const float* __restrict__ bias,
                                  const float* __restrict__ W, float* __restrict__ out) {
    __shared__ float Ws[F * FO];
    __shared__ float bs[F];
    int tid = threadIdx.x;
    if (tid < F * FO) Ws[tid] = W[tid];
    if (tid < F) bs[tid] = bias[tid];
    __syncthreads();
    int i = blockIdx.x * blockDim.x + tid;
    if (i >= NN) return;
    float dd = dis[i];
    float v[F];
#pragma unroll
    for (int f = 0; f < F; f++)
        v[f] = fmaxf(dd * (agg[(size_t)i * F + f] + hs[(size_t)i * F + f]) + bs[f], 0.f);
#pragma unroll
    for (int fo = 0; fo < FO; fo++) {
        float s = 0.f;
#pragma unroll
        for (int f = 0; f < F; f++) s = fmaf(v[f], Ws[f * FO + fo], s);
        out[(size_t)i * FO + fo] = dd * s;
    }
}

__global__ void combine_pool(const float* __restrict__ agg, const float* __restrict__ hs,
                             const float* __restrict__ dis, const float* __restrict__ bias,
                             const int* __restrict__ batch, float* __restrict__ pool) {
    __shared__ float bs[16];
    int tid = threadIdx.x;
    if (tid < 16) bs[tid] = bias[tid];
    __syncthreads();
    int i = blockIdx.x * blockDim.x + tid;
    if (i >= NN) return;
    float dd = dis[i];
    float v[16];
#pragma unroll
    for (int f = 0; f < 16; f++)
        v[f] = fmaxf(dd * (agg[(size_t)i * 16 + f] + hs[(size_t)i * 16 + f]) + bs[f], 0.f);
    int bb = batch[i];
    unsigned m = __activemask();
    bool uni = false;
    if (m == 0xffffffffu) {
        int bb0 = __shfl_sync(0xffffffffu, bb, 0);
        uni = __all_sync(0xffffffffu, bb == bb0);
    }
    int* p = reinterpret_cast<int*>(pool + (size_t)bb * 16);
    if (uni) {
#pragma unroll
        for (int f = 0; f < 16; f++) {
            float t = v[f];
#pragma unroll
            for (int o = 16; o; o >>= 1) t = fmaxf(t, __shfl_xor_sync(0xffffffffu, t, o));
            v[f] = t;
        }
        if ((tid & 31) == 0)
#pragma unroll
            for (int f = 0; f < 16; f++) atomicMax(&p[f], __float_as_int(v[f]));
    } else {
#pragma unroll
        for (int f = 0; f < 16; f++) atomicMax(&p[f], __float_as_int(v[f]));
    }
}

// ------------------------ generic GEMM (f32x2) -------------------------------
__global__ void gemm_kernel(const float* __restrict__ A, const float* __restrict__ W,
                            const float* __restrict__ bias, float* __restrict__ C,
                            int M, int K, int Nc, int ldc, int coloff, int relu) {
    const int BM = 64, BN = 64, BK = 8;
    __shared__ __align__(16) float As[BK][BM];
    __shared__ __align__(16) float Bs[BK][BN];
    int tid = threadIdx.x;
    int tc = tid & 15, tr = tid >> 4;
    int brow = blockIdx.y * BM, bcol = blockIdx.x * BN;
    ull acc[4][2] = {};
    for (int k0 = 0; k0 < K; k0 += BK) {
        for (int i = tid; i < BM * BK; i += 256) {
            int kk = i & 7, m = i >> 3;
            int gr = brow + m, gc = k0 + kk;
            As[kk][m] = (gr < M && gc < K) ? A[(size_t)gr * K + gc] : 0.f;
        }
        for (int i = tid; i < BN * BK; i += 256) {
            int n = i & 63, kk = i >> 6;
            int gc = bcol + n, gr = k0 + kk;
            Bs[kk][n] = (gr < K && gc < Nc) ? W[(size_t)gr * Nc + gc] : 0.f;
        }
        __syncthreads();
#pragma unroll
        for (int kk = 0; kk < BK; kk++) {
            ull b0 = *reinterpret_cast<const ull*>(&Bs[kk][tc * 4]);
            ull b1 = *reinterpret_cast<const ull*>(&Bs[kk][tc * 4 + 2]);
            float4 av = *reinterpret_cast<const float4*>(&As[kk][tr * 4]);
            float aa[4] = {av.x, av.y, av.z, av.w};
#pragma unroll
            for (int u = 0; u < 4; u++) {
                ull a2 = pk2(aa[u], aa[u]);
                ffma2(acc[u][0], b0, a2);
                ffma2(acc[u][1], b1, a2);
            }
        }
        __syncthreads();
    }
#pragma unroll
    for (int u = 0; u < 4; u++) {
        int r = brow + tr * 4 + u;
        if (r >= M) continue;
#pragma unroll
        for (int v2 = 0; v2 < 2; v2++) {
            float2 pv = upk2(acc[u][v2]);
            float vals[2] = {pv.x, pv.y};
#pragma unroll
            for (int w = 0; w < 2; w++) {
                int c = bcol + tc * 4 + v2 * 2 + w;
                if (c >= Nc) continue;
                float val = vals[w] + bias[c];
                if (relu) val = fmaxf(val, 0.f);
                C[(size_t)r * ldc + coloff + c] = val;
            }
        }
    }
}

// ------------------------ conv1 (scalar f32x2) -------------------------------
__device__ __forceinline__ void load_e10(const float* __restrict__ xA, ull e[10]) {
    const ulonglong2* pA = reinterpret_cast<const ulonglong2*>(xA);
#pragma unroll
    for (int i = 0; i < 5; i++) {
        ulonglong2 va = pA[i]; e[2 * i] = va.x; e[2 * i + 1] = va.y;
    }
}
__device__ __forceinline__ void make_o8(const ull e[10], ull o[8]) {
#pragma unroll
    for (int j = 0; j < 8; j++)
        o[j] = (e[j] >> 32) | (e[j + 1] << 32);
}

__device__ __forceinline__ void ic_upd_1oc(const float* __restrict__ xA,
                                           const float* __restrict__ w, ull a0[5]) {
    ull e[10], o[8];
    load_e10(xA, e); make_o8(e, o);
#pragma unroll
    for (int k = 0; k < 8; k++) {
        float wv = w[k * 33];
        ull w2 = pk2(wv, wv);
        const ull* xpp = (k & 1) ? &o[k >> 1] : &e[k >> 1];
#pragma unroll
        for (int j = 0; j < 5; j++) ffma2(a0[j], xpp[j], w2);
    }
}

__device__ __forceinline__ void unpack9(const ull acc[5], float a[9]) {
#pragma unroll
    for (int j = 0; j < 4; j++) {
        float2 t = upk2(acc[j]);
        a[2 * j] = t.x; a[2 * j + 1] = t.y;
    }
    a[8] = upk2(acc[4]).x;
}

__global__ void conv1_kernel(const float* __restrict__ tgt, const float* __restrict__ K1,
                             const float* __restrict__ cb1, float* __restrict__ out) {
    __shared__ __align__(16) float inA[5 * 8 * 20];
    __shared__ float w_s[40 * 33];
    __shared__ float b_s[32];
    int b = blockIdx.x;
    int g0 = blockIdx.y * 8;
    int tx = threadIdx.x, ty = threadIdx.y;
    int tid = ty * 32 + tx;
    int L0 = g0 * 9;
    for (int i = tid; i < 800; i += 256) {
        int c = i / 160, r = i % 160, t = r / 20, j = r % 20;
        int l = L0 + t * 9 + j;
        inA[i] = (l < LL) ? tgt[(size_t)b * (LL * 5) + l * 5 + c] : 0.f;
    }
    for (int i = tid; i < 2048; i += 256) {
        int oc = i >> 6, r = i & 63;
        if (r < 40) w_s[r * 33 + oc] = K1[oc * 40 + r];
    }
    if (tid < 32) b_s[tid] = cb1[tid];
    __syncthreads();

    ull acc[5] = {};
#pragma unroll
    for (int ic = 0; ic < 5; ic++)
        ic_upd_1oc(&inA[(ic * 8 + ty) * 20], &w_s[ic * 8 * 33 + tx], acc);
    float a[9]; unpack9(acc, a);
    float bb = b_s[tx];
    int grp = g0 + ty;
#pragma unroll
    for (int p = 0; p < 3; p++) {
        int po = grp * 3 + p;
        if (po < 331) {
            float v = fmaxf(fmaxf(a[3 * p], a[3 * p + 1]), a[3 * p + 2]) + bb;
            out[((size_t)b * 32 + tx) * 331 + po] = fmaxf(v, 0.f);
        }
    }
}

// ------------------------ conv2: 2-term TF32 implicit GEMM -------------------
// D = (Wh + Wl) . Xh   (x-residual term dropped; err ~2^-12 rel)
// smem: xh[32*200] | wh[64*33] | wl[64*33]; dump D[64][200] reuses base.
#define C2M_WH  6400
#define C2M_WL  (6400 + 2112)
#define CONV2M_SMEM (12800 * 4)    // max(10624 compute, 12800 dump)
__global__ void __launch_bounds__(256, 2) conv2_mma(
        const float* __restrict__ c1, const float* __restrict__ K2,
        const float* __restrict__ cb2, float* __restrict__ out) {
    extern __shared__ __align__(16) float sm[];
    float* xh = sm;
    float* wh = sm + C2M_WH;
    float* wl = sm + C2M_WL;
    int b = blockIdx.x, z = blockIdx.y;
    int tid = threadIdx.x;
    int lane = tid & 31, w = tid >> 5;
    int wm = w >> 2, wn = w & 3;            // 2 m-groups x 4 n-quarters
    int g = lane >> 2, tg = lane & 3;
    int base = z * 168;

    for (int i = tid; i < 6400; i += 256) {
        int ic = i / 200, j = i % 200;
        int l = base + j;
        float v = (l < 331) ? c1[((size_t)b * 32 + ic) * 331 + l] : 0.f;
        xh[i] = tf32_hi(v);
    }

    float acc[2][6][4] = {};
    for (int s = 0; s < 8; s++) {
        __syncthreads();
        for (int i = tid; i < 2048; i += 256) {
            int oc = i >> 5, rr = i & 31;
            float v = K2[(size_t)oc * 256 + s * 32 + rr];
            float h = tf32_hi(v);
            wh[oc * 33 + rr] = h;
            wl[oc * 33 + rr] = tf32_hi(v - h);
        }
        __syncthreads();
#pragma unroll
        for (int ks = 0; ks < 4; ks++) {
            int ic = s * 4 + ks;
            const float* xrh = xh + ic * 200;
            uint bh0[6], bh1[6];
#pragma unroll
            for (int nt = 0; nt < 6; nt++) {
                int ai = (wn * 6 + nt) * 8 + g + tg;
                bh0[nt] = __float_as_uint(xrh[ai]);
                bh1[nt] = __float_as_uint(xrh[ai + 4]);
            }
#pragma unroll
            for (int mt = 0; mt < 2; mt++) {
                int ocr = wm * 32 + mt * 16 + g;
                int col = ks * 8 + tg;
                uint ah0 = __float_as_uint(wh[ocr * 33 + col]);
                uint ah1 = __float_as_uint(wh[(ocr + 8) * 33 + col]);
                uint ah2 = __float_as_uint(wh[ocr * 33 + col + 4]);
                uint ah3 = __float_as_uint(wh[(ocr + 8) * 33 + col + 4]);
                uint al0 = __float_as_uint(wl[ocr * 33 + col]);
                uint al1 = __float_as_uint(wl[(ocr + 8) * 33 + col]);
                uint al2 = __float_as_uint(wl[ocr * 33 + col + 4]);
                uint al3 = __float_as_uint(wl[(ocr + 8) * 33 + col + 4]);
#pragma unroll
                for (int nt = 0; nt < 6; nt++) {
                    mma_tf32(acc[mt][nt], al0, al1, al2, al3, bh0[nt], bh1[nt]);
                    mma_tf32(acc[mt][nt], ah0, ah1, ah2, ah3, bh0[nt], bh1[nt]);
                }
            }
        }
    }
    __syncthreads();
    float* dump = sm;
#pragma unroll
    for (int mt = 0; mt < 2; mt++) {
        int ocr = wm * 32 + mt * 16 + g;
#pragma unroll
        for (int nt = 0; nt < 6; nt++) {
            int n0 = (wn * 6 + nt) * 8 + 2 * tg;
            dump[ocr * 200 + n0]           = acc[mt][nt][0];
            dump[ocr * 200 + n0 + 1]       = acc[mt][nt][1];
            dump[(ocr + 8) * 200 + n0]     = acc[mt][nt][2];
            dump[(ocr + 8) * 200 + n0 + 1] = acc[mt][nt][3];
        }
    }
    __syncthreads();
    if (tid < 64) {
        float bb = cb2[tid];
        const float* row = dump + tid * 200;
        float* orow = out + ((size_t)b * 64 + tid) * 108 + z * 56;
#pragma unroll
        for (int g2 = 0; g2 < 56; g2++) {
            int po = z * 56 + g2;
            if (po < 108) {
                float v = fmaxf(fmaxf(row[3 * g2], row[3 * g2 + 1]), row[3 * g2 + 2]) + bb;
                orow[g2] = fmaxf(v, 0.f);
            }
        }
    }
}

// ------------------------ conv3: 2-term TF32 implicit GEMM -------------------
// smem: xh[64*112] | wh[128*33] | wl[128*33]; dump D[128][112] reuses base.
#define C3M_WH  7168
#define C3M_WL  (7168 + 4224)
#define CONV3M_SMEM ((7168 + 2 * 4224) * 4)   // 15616 floats >= dump 14336
__global__ void __launch_bounds__(256, 2) conv3_mma(
        const float* __restrict__ c2, const float* __restrict__ K3,
        const float* __restrict__ cb3, float* __restrict__ c3) {
    extern __shared__ __align__(16) float sm[];
    float* xh = sm;
    float* wh = sm + C3M_WH;
    float* wl = sm + C3M_WL;
    int b = blockIdx.x;
    int tid = threadIdx.x;
    int lane = tid & 31, w = tid >> 5;
    int wm = w >> 1, wn = w & 1;           // 4 m-groups x 2 n-halves
    int g = lane >> 2, tg = lane & 3;

    for (int i = tid; i < 7168; i += 256) {
        int ic = i / 112, l = i % 112;
        float v = (l < 108) ? c2[(size_t)b * 6912 + ic * 108 + l] : 0.f;
        xh[i] = tf32_hi(v);
    }

    float acc[2][7][4] = {};
    for (int s = 0; s < 16; s++) {
        __syncthreads();
        for (int i = tid; i < 4096; i += 256) {
            int oc = i >> 5, rr = i & 31;
            float v = K3[(size_t)oc * 512 + s * 32 + rr];
            float h = tf32_hi(v);
            wh[oc * 33 + rr] = h;
            wl[oc * 33 + rr] = tf32_hi(v - h);
        }
        __syncthreads();
#pragma unroll
        for (int ks = 0; ks < 4; ks++) {
            int ic = s * 4 + ks;
            const float* xrh = xh + ic * 112;
            uint bh0[7], bh1[7];
#pragma unroll
            for (int nt = 0; nt < 7; nt++) {
                int ai = (wn * 7 + nt) * 8 + g + tg;
                bh0[nt] = __float_as_uint(xrh[ai]);
                bh1[nt] = __float_as_uint(xrh[ai + 4]);
            }
#pragma unroll
            for (int mt = 0; mt < 2; mt++) {
                int ocr = wm * 32 + mt * 16 + g;
                int col = ks * 8 + tg;
                uint ah0 = __float_as_uint(wh[ocr * 33 + col]);
                uint ah1 = __float_as_uint(wh[(ocr + 8) * 33 + col]);
                uint ah2 = __float_as_uint(wh[ocr * 33 + col + 4]);
                uint ah3 = __float_as_uint(wh[(ocr + 8) * 33 + col + 4]);
                uint al0 = __float_as_uint(wl[ocr * 33 + col]);
                uint al1 = __float_as_uint(wl[(ocr + 8) * 33 + col]);
                uint al2 = __float_as_uint(wl[ocr * 33 + col + 4]);
                uint al3 = __float_as_uint(wl[(ocr + 8) * 33 + col + 4]);
#pragma unroll
                for (int nt = 0; nt < 7; nt++) {
                    mma_tf32(acc[mt][nt], al0, al1, al2, al3, bh0[nt], bh1[nt]);
                    mma_tf32(acc[mt][nt], ah0, ah1, ah2, ah3, bh0[nt], bh1[nt]);
                }
            }
        }
    }
    __syncthreads();
    float* dump = sm;
#pragma unroll
    for (int mt = 0; mt < 2; mt++) {
        int ocr = wm * 32 + mt * 16 + g;
#pragma unroll
        for (int nt = 0; nt < 7; nt++) {
            int n0 = (wn * 7 + nt) * 8 + 2 * tg;
            dump[ocr * 112 + n0]           = acc[mt][nt][0];
            dump[ocr * 112 + n0 + 1]       = acc[mt][nt][1];
            dump[(ocr + 8) * 112 + n0]     = acc[mt][nt][2];
            dump[(ocr + 8) * 112 + n0 + 1] = acc[mt][nt][3];
        }
    }
    __syncthreads();
    if (tid < 128) {
        float bb = cb3[tid];
        const float* row = dump + tid * 112;
        float ssum = 0.f;
#pragma unroll
        for (int gp = 0; gp < 33; gp++) {
            float v = fmaxf(fmaxf(row[3 * gp], row[3 * gp + 1]), row[3 * gp + 2]) + bb;
            ssum += fmaxf(v, 0.f);
        }
        c3[(size_t)b * 128 + tid] = ssum * (1.0f / 33.0f);
    }
}

// ------------------------ stream fork/join context --------------------------
struct Ctx {
    cudaStream_t s2 = nullptr;
    cudaEvent_t eF = nullptr, eJ = nullptr;
    bool ok = false;
    Ctx() {
        ok = (cudaStreamCreateWithFlags(&s2, cudaStreamNonBlocking) == cudaSuccess) &&
             (cudaEventCreateWithFlags(&eF, cudaEventDisableTiming) == cudaSuccess) &&
             (cudaEventCreateWithFlags(&eJ, cudaEventDisableTiming) == cudaSuccess);
    }
};
static Ctx g_ctx;

// ------------------------ host orchestration --------------------------------
extern "C" void kernel_launch(void* const* d_in, const int* in_sizes, int n_in,
                              void* d_out, int out_size) {
    const float* x    = (const float*)d_in[0];
    const int*   ei   = (const int*)d_in[1];
    const int*   batch= (const int*)d_in[2];
    const float* tgt  = (const float*)d_in[3];
    const float* W1 = (const float*)d_in[4];   const float* b1 = (const float*)d_in[5];
    const float* W2 = (const float*)d_in[6];   const float* b2 = (const float*)d_in[7];
    const float* W3 = (const float*)d_in[8];   const float* b3 = (const float*)d_in[9];
    const float* Wg1= (const float*)d_in[10];  const float* bg1= (const float*)d_in[11];
    const float* Wg2= (const float*)d_in[12];  const float* bg2= (const float*)d_in[13];
    const float* K1 = (const float*)d_in[14];  const float* cb1= (const float*)d_in[15];
    const float* K2 = (const float*)d_in[16];  const float* cb2= (const float*)d_in[17];
    const float* K3 = (const float*)d_in[18];  const float* cb3= (const float*)d_in[19];
    const float* Wxt= (const float*)d_in[20];  const float* bxt= (const float*)d_in[21];
    const float* Wf1= (const float*)d_in[22];  const float* bf1= (const float*)d_in[23];
    const float* Wf2= (const float*)d_in[24];  const float* bf2= (const float*)d_in[25];
    const float* Wo = (const float*)d_in[26];  const float* bo = (const float*)d_in[27];
    float* out = (float*)d_out;

    float *p_dis, *p_h, *p_feat, *p_agg, *p_pool, *p_t1, *p_xc, *p_c1, *p_c2, *p_c3, *p_f1, *p_f2;
    int* p_deg;
    cudaGetSymbolAddress((void**)&p_dis, g_dis);
    cudaGetSymbolAddress((void**)&p_deg, g_deg);
    cudaGetSymbolAddress((void**)&p_h, g_h);
    cudaGetSymbolAddress((void**)&p_feat, g_feat);
    cudaGetSymbolAddress((void**)&p_agg, g_agg);
    cudaGetSymbolAddress((void**)&p_pool, g_pool);
    cudaGetSymbolAddress((void**)&p_t1, g_t1);
    cudaGetSymbolAddress((void**)&p_xc, g_xc);
    cudaGetSymbolAddress((void**)&p_c1, g_c1);
    cudaGetSymbolAddress((void**)&p_c2, g_c2);
    cudaGetSymbolAddress((void**)&p_c3, g_c3);
    cudaGetSymbolAddress((void**)&p_f1, g_f1);
    cudaGetSymbolAddress((void**)&p_f2, g_f2);

    const int TPB = 256;
    const int gE = (EE + TPB - 1) / TPB;
    const int gN = (NN + TPB - 1) / TPB;

    bool fork = g_ctx.ok;
    cudaStream_t sg = fork ? g_ctx.s2 : (cudaStream_t)0;

    if (fork) {
        cudaEventRecord(g_ctx.eF, 0);
        cudaStreamWaitEvent(sg, g_ctx.eF, 0);
    }

    cudaFuncSetAttribute(conv2_mma, cudaFuncAttributeMaxDynamicSharedMemorySize, CONV2M_SMEM);
    cudaFuncSetAttribute(conv3_mma, cudaFuncAttributeMaxDynamicSharedMemorySize, CONV3M_SMEM);

    // Submission order: conv3_mma is the 6th launch (ncu -s 5 -c 1 window).
    cudaMemsetAsync(p_deg, 0, NN * sizeof(int), sg);                                 // 1
    deg_kernel<<<gE, TPB, 0, sg>>>(ei, p_deg);                                       // 2
    conv1_kernel<<<dim3(BB, 14), dim3(32, 8)>>>(tgt, K1, cb1, p_c1);                 // 3
    cudaMemsetAsync(p_c3, 0, BB * 128 * sizeof(float));                              // 4
    conv2_mma<<<dim3(BB, 2), 256, CONV2M_SMEM>>>(p_c1, K2, cb2, p_c2);               // 5
    conv3_mma<<<BB, 256, CONV3M_SMEM>>>(p_c2, K3, cb3, p_c3);                        // 6 <- profiled
    gemm_kernel<<<dim3(2, 8), 256>>>(p_c3, Wxt, bxt, p_xc, BB, 128, 128, 256, 128, 1);

    // ---- graph branch (stream sg) ----
    dis_kernel<<<gN, TPB, 0, sg>>>(p_deg, p_dis);
    transform1<<<gN, TPB, 0, sg>>>(x, W1, p_dis, p_h);
    cudaMemsetAsync(p_agg, 0, (size_t)NN * 4 * sizeof(float), sg);
    scatter_kernel<4><<<gE, TPB, 0, sg>>>(ei, p_h, p_agg);
    combine_transform<4, 8><<<gN, TPB, 0, sg>>>(p_agg, p_h, p_dis, b1, W2, p_feat);

    cudaMemsetAsync(p_agg, 0, (size_t)NN * 8 * sizeof(float), sg);
    scatter_kernel<8><<<gE, TPB, 0, sg>>>(ei, p_feat, p_agg);
    combine_transform<8, 16><<<gN, TPB, 0, sg>>>(p_agg, p_feat, p_dis, b2, W3, p_h);

    cudaMemsetAsync(p_agg, 0, (size_t)NN * 16 * sizeof(float), sg);
    scatter_kernel<16><<<gE, TPB, 0, sg>>>(ei, p_h, p_agg);
    cudaMemsetAsync(p_pool, 0, BB * 16 * sizeof(float), sg);
    combine_pool<<<gN, TPB, 0, sg>>>(p_agg, p_h, p_dis, b3, batch, p_pool);

    gemm_kernel<<<dim3(16, 8), 256, 0, sg>>>(p_pool, Wg1, bg1, p_t1, BB, 16, 1024, 1024, 0, 1);
    gemm_kernel<<<dim3(2, 8), 256, 0, sg>>>(p_t1, Wg2, bg2, p_xc, BB, 1024, 128, 256, 0, 0);
    if (fork) cudaEventRecord(g_ctx.eJ, sg);

    // ---- join + fusion head (stream 0) ----
    if (fork) cudaStreamWaitEvent(0, g_ctx.eJ, 0);
    gemm_kernel<<<dim3(16, 8), 256>>>(p_xc, Wf1, bf1, p_f1, BB, 256, 1024, 1024, 0, 1);
    gemm_kernel<<<dim3(8, 8), 256>>>(p_f1, Wf2, bf2, p_f2, BB, 1024, 512, 512, 0, 1);
    gemm_kernel<<<dim3(1, 8), 256>>>(p_f2, Wo, bo, out, BB, 512, 2, 2, 0, 0);
}